// round 8
// baseline (speedup 1.0000x reference)
#include <cuda_runtime.h>
#include <cuda_fp16.h>
#include <cstdint>

#define BATCH 4
#define CIN   320
#define COUT  320
#define HW    4096
#define CK    2880           // K = c*9 + k (native weight layout)
#define CAT2  640
#define STGB  35840          // A 128x80B=10240 + B 320x80B=25600
#define SMEMB_BIG 84480      // max(2*STGB=71680, epilogue 160*132*4)
#define SMEMB_DU  174080     // D1 102400 + 2*35840 phase1 stages
#define SMEMB_IM  167936     // planes 131072 + stage 36864

// ---------------- device scratch ----------------
__device__ __half g_Ac[(size_t)BATCH*HW*CK];
__device__ __half g_Ad[(size_t)BATCH*HW*CK];
__device__ __half g_wt[COUT*CK];
__device__ __half g_wd[COUT*CAT2];
__device__ __half g_wu[COUT*COUT];
__device__ __half g_ct[(size_t)BATCH*HW*CAT2];
__device__ float  g_hF[(size_t)BATCH*COUT*HW];
__device__ int    g_ci[9*HW];
__device__ float  g_cw[9*HW];
__device__ int4   g_idf[9*HW];
__device__ float4 g_wdf[9*HW];

// ---------------- helpers ----------------
__device__ __forceinline__ uint32_t smem_u32(const void* p) {
    uint32_t a;
    asm("{ .reg .u64 t; cvta.to.shared.u64 t, %1; cvt.u32.u64 %0, t; }" : "=r"(a) : "l"(p));
    return a;
}
__device__ __forceinline__ void cpa16(uint32_t dst, const void* src) {
    asm volatile("cp.async.cg.shared.global [%0], [%1], 16;" :: "r"(dst), "l"(src));
}
#define LDM4(r, addr) \
    asm volatile("ldmatrix.sync.aligned.m8n8.x4.shared.b16 {%0,%1,%2,%3}, [%4];" \
        : "=r"((r)[0]), "=r"((r)[1]), "=r"((r)[2]), "=r"((r)[3]) : "r"(addr))
#define MMA_F16(c, a, bq) \
    asm volatile("mma.sync.aligned.m16n8k16.row.col.f32.f16.f16.f32 " \
        "{%0,%1,%2,%3}, {%4,%5,%6,%7}, {%8,%9}, {%0,%1,%2,%3};" \
        : "+f"((c)[0]), "+f"((c)[1]), "+f"((c)[2]), "+f"((c)[3]) \
        : "r"((a)[0]), "r"((a)[1]), "r"((a)[2]), "r"((a)[3]), "r"((bq)[0]), "r"((bq)[1]))

__device__ __forceinline__ uint32_t hpack(__half a, __half b) {
    return (uint32_t)__half_as_ushort(a) | ((uint32_t)__half_as_ushort(b) << 16);
}

// ---------------- launch #1: table precompute ----------------
__global__ void precompute(const float* __restrict__ off) {
    int t = blockIdx.x * 256 + threadIdx.x;
    if (t >= 9 * HW) return;
    int k = t >> 12, p = t & 4095;
    int r = p >> 6, c = p & 63;
    int rr = r + k / 3 - 1, qq = c + k % 3 - 1;
    bool vb = (rr >= 0 && rr < 64 && qq >= 0 && qq < 64);
    g_ci[t] = vb ? rr * 64 + qq : 0;
    g_cw[t] = vb ? 1.f : 0.f;
    float dy = off[((k*2+0) << 12) + p];
    float dx = off[((k*2+1) << 12) + p];
    float py = (float)rr + dy, px = (float)qq + dx;
    float y0f = floorf(py), x0f = floorf(px);
    int y0 = (int)y0f, x0 = (int)x0f;
    float wy = py - y0f, wx = px - x0f;
    float wv[4] = { (1.f-wy)*(1.f-wx), (1.f-wy)*wx, wy*(1.f-wx), wy*wx };
    int   idx[4]; float wgt[4];
#pragma unroll
    for (int j = 0; j < 4; j++) {
        int yy = y0 + (j >> 1), xx = x0 + (j & 1);
        bool ok = (yy >= 0 && yy < 64 && xx >= 0 && xx < 64);
        idx[j] = (min(max(yy,0),63) << 6) + min(max(xx,0),63);
        wgt[j] = ok ? wv[j] : 0.f;
    }
    g_idf[t] = make_int4(idx[0], idx[1], idx[2], idx[3]);
    g_wdf[t] = make_float4(wgt[0], wgt[1], wgt[2], wgt[3]);
}

// ---------------- launch #2: all weight conversions in one kernel ----------------
#define NW1 (COUT*CK)
#define NW2 (COUT*CAT2)
#define NW3 (COUT*COUT)
__global__ void prep_w(const float* __restrict__ w, const float* __restrict__ wdn,
                       const float* __restrict__ wup,
                       __half* wt, __half* wd, __half* wu) {
    int i = blockIdx.x * 256 + threadIdx.x;
    if (i < NW1) wt[i] = __float2half_rn(w[i]);
    else if (i < NW1 + NW2) wd[i - NW1] = __float2half_rn(wdn[i - NW1]);
    else if (i < NW1 + NW2 + NW3) wu[i - NW1 - NW2] = __float2half_rn(wup[i - NW1 - NW2]);
}

// ---------------- launch #3: fused im2col, smem-staged coalesced writes ----------------
__global__ __launch_bounds__(256) void im2col_fused(
    const float* __restrict__ x,
    __half* __restrict__ Ac, __half* __restrict__ Ad)
{
    extern __shared__ char sm[];
    float* pl = (float*)sm;                       // 8 planes, 128KB
    __half* stg = (__half*)(sm + 131072);         // 256 pix x 72 halves
    int b  = blockIdx.y;
    int c0 = blockIdx.x * 8;
    int tid = threadIdx.x;
    for (int idx = tid; idx < 8 * 4096; idx += 256)
        pl[idx] = x[(((size_t)b * CIN + c0) << 12) + idx];
    __syncthreads();

    for (int p0 = 0; p0 < 4096; p0 += 256) {
        int p = p0 + tid;
        // ---- conv taps ----
#pragma unroll
        for (int k = 0; k < 9; k++) {
            int   ci = g_ci[(k << 12) + p];
            float cw = g_cw[(k << 12) + p];
#pragma unroll
            for (int c = 0; c < 8; c++)
                stg[tid * 72 + c * 9 + k] = __float2half_rn(cw * pl[(c << 12) + ci]);
        }
        __syncthreads();
#pragma unroll
        for (int j = 0; j < 9; j++) {
            int idx = j * 256 + tid;
            int pix = idx / 9, off = idx - pix * 9;
            uint4 v = ((const uint4*)(stg + pix * 72))[off];
            *(uint4*)(Ac + ((size_t)(b * HW) + p0 + pix) * CK + c0 * 9 + off * 8) = v;
        }
        __syncthreads();
        // ---- deformable taps ----
#pragma unroll
        for (int k = 0; k < 9; k++) {
            int4   di = g_idf[(k << 12) + p];
            float4 dw = g_wdf[(k << 12) + p];
#pragma unroll
            for (int c = 0; c < 8; c++) {
                const float* q = pl + (c << 12);
                float v = dw.x*q[di.x] + dw.y*q[di.y] + dw.z*q[di.z] + dw.w*q[di.w];
                stg[tid * 72 + c * 9 + k] = __float2half_rn(v);
            }
        }
        __syncthreads();
#pragma unroll
        for (int j = 0; j < 9; j++) {
            int idx = j * 256 + tid;
            int pix = idx / 9, off = idx - pix * 9;
            uint4 v = ((const uint4*)(stg + pix * 72))[off];
            *(uint4*)(Ad + ((size_t)(b * HW) + p0 + pix) * CK + c0 * 9 + off * 8) = v;
        }
        __syncthreads();
    }
}

// ---------------- launch #4: big dual GEMM (conv + deformable) ----------------
// D[128 pix][320 ch] = A[pix][K] * wt[ch][K] + bias. y=0: A=def -> ct[:,0:320];
// y=1: A=conv -> ct[:,320:640] and hF (f32 ch-major).
__global__ void __launch_bounds__(256, 1) gemm_big(
    const __half* __restrict__ Ad, const __half* __restrict__ Ac,
    const __half* __restrict__ B,
    const float* __restrict__ bias, float* __restrict__ hF,
    __half* __restrict__ O)
{
    extern __shared__ char smem[];
    uint32_t sb = smem_u32(smem);
    float* fst = (float*)smem;
    int tid = threadIdx.x;
    int b = blockIdx.z;
    int pix0 = blockIdx.x * 128;
    int yy = blockIdx.y;
    const int NCH = CK >> 5;

    const __half* Ab = (yy ? Ac : Ad) + (size_t)(b * HW + pix0) * CK;
    int cofs = yy ? 320 : 0;

    int w = tid >> 5, lane = tid & 31;
    int m0 = (w & 3) * 32;
    int ng = w >> 2;
    int a_r = (lane & 7) + ((lane >> 3) & 1) * 8;
    int a_c = ((lane >> 4) & 1) * 16;
    int b_r = (lane & 7) + ((lane >> 4) & 1) * 8;
    int b_c = ((lane >> 3) & 1) * 16;

    float acc[2][20][4];
#pragma unroll
    for (int i = 0; i < 2; i++)
#pragma unroll
        for (int j = 0; j < 20; j++)
#pragma unroll
            for (int q = 0; q < 4; q++) acc[i][j][q] = 0.f;

    auto load_stage = [&](int ci) {
        uint32_t st = sb + (uint32_t)(ci & 1) * STGB;
        int k0 = ci << 5;
        {
            int r = tid >> 1, j = tid & 1;
            cpa16(st + r * 80 + j * 32,      Ab + (size_t)r * CK + k0 + j * 16);
            cpa16(st + r * 80 + j * 32 + 16, Ab + (size_t)r * CK + k0 + j * 16 + 8);
        }
#pragma unroll
        for (int it = 0; it < 5; it++) {
            int idx = tid + it * 256;
            int r = idx >> 2, j = idx & 3;
            cpa16(st + 10240 + r * 80 + j * 16, B + (size_t)r * CK + k0 + j * 8);
        }
        asm volatile("cp.async.commit_group;" ::: "memory");
    };

    load_stage(0);
    for (int i = 0; i < NCH; i++) {
        if (i + 1 < NCH) {
            load_stage(i + 1);
            asm volatile("cp.async.wait_group 1;" ::: "memory");
        } else {
            asm volatile("cp.async.wait_group 0;" ::: "memory");
        }
        __syncthreads();
        uint32_t st = sb + (uint32_t)(i & 1) * STGB;
#pragma unroll
        for (int kk = 0; kk < 2; kk++) {
            uint32_t ah[2][4];
#pragma unroll
            for (int mf = 0; mf < 2; mf++) {
                uint32_t ad = st + (uint32_t)(m0 + mf * 16 + a_r) * 80 + kk * 32 + a_c;
                LDM4(ah[mf], ad);
            }
#pragma unroll
            for (int np = 0; np < 10; np++) {
                uint32_t bh[4];
                uint32_t bd = st + 10240 + (uint32_t)(ng * 160 + np * 16 + b_r) * 80 + kk * 32 + b_c;
                LDM4(bh, bd);
#pragma unroll
                for (int mf = 0; mf < 2; mf++)
#pragma unroll
                    for (int h = 0; h < 2; h++)
                        MMA_F16(acc[mf][np * 2 + h], ah[mf], bh + 2 * h);
            }
        }
        __syncthreads();
    }

    for (int g = 0; g < 2; g++) {
        if (ng == g) {
#pragma unroll
            for (int mf = 0; mf < 2; mf++)
#pragma unroll
                for (int nf = 0; nf < 20; nf++) {
                    int pr = m0 + mf * 16 + (lane >> 2);
                    int nc = nf * 8 + 2 * (lane & 3);
                    fst[nc * 132 + pr]           = acc[mf][nf][0];
                    fst[(nc + 1) * 132 + pr]     = acc[mf][nf][1];
                    fst[nc * 132 + pr + 8]       = acc[mf][nf][2];
                    fst[(nc + 1) * 132 + pr + 8] = acc[mf][nf][3];
                }
        }
        __syncthreads();
        int chbase = g * 160;

        if (yy == 1) {
            for (int idx = tid; idx < 160 * 128; idx += 256) {
                int n = idx >> 7, p = idx & 127;
                float v = fst[n * 132 + p] + __ldg(bias + chbase + n);
                hF[(((size_t)b * COUT + chbase + n) << 12) + pix0 + p] = v;
            }
        }
        {
            int p = tid >> 1, hf2 = tid & 1;
            int cb = chbase + hf2 * 80;
            size_t row = ((size_t)(b * HW) + pix0 + p) * CAT2 + cofs + cb;
            uint32_t uh[40];
#pragma unroll
            for (int m = 0; m < 40; m++) {
                int n = hf2 * 80 + 2 * m;
                float v0 = fst[n * 132 + p] + __ldg(bias + chbase + n);
                float v1 = fst[(n + 1) * 132 + p] + __ldg(bias + chbase + n + 1);
                uh[m] = hpack(__float2half_rn(v0), __float2half_rn(v1));
            }
#pragma unroll
            for (int q = 0; q < 10; q++)
                ((uint4*)(O + row))[q] = make_uint4(uh[4*q], uh[4*q+1], uh[4*q+2], uh[4*q+3]);
        }
        __syncthreads();
    }
}

// ---------------- launch #5: fused down+up GEMM ----------------
// D1[128][320] = ct[pix][0:640] @ wd^T  (fp16 in smem)
// out = hF + scale * (D1 @ wu^T)        (f32 ch-major)
__global__ void __launch_bounds__(256, 1) gemm_downup(
    const __half* __restrict__ ct, const __half* __restrict__ wd,
    const __half* __restrict__ wu,
    const float* __restrict__ hF, float* __restrict__ out,
    const float* __restrict__ scalep)
{
    extern __shared__ char smem[];
    uint32_t sb = smem_u32(smem);
    float* fst = (float*)smem;
    uint32_t d1  = sb;              // 10 chunks x 10240 = 102400
    uint32_t st1 = sb + 102400;     // phase1 stages: 2 x 35840
    uint32_t st2 = sb + 102400;     // phase2 B stages: 2 x 25600
    int tid = threadIdx.x;
    int b = blockIdx.y;
    int pix0 = blockIdx.x * 128;

    const __half* Ab = ct + (size_t)(b * HW + pix0) * CAT2;

    int w = tid >> 5, lane = tid & 31;
    int m0 = (w & 3) * 32;
    int ng = w >> 2;
    int a_r = (lane & 7) + ((lane >> 3) & 1) * 8;
    int a_c = ((lane >> 4) & 1) * 16;
    int b_r = (lane & 7) + ((lane >> 4) & 1) * 8;
    int b_c = ((lane >> 3) & 1) * 16;

    float acc[2][20][4];
#pragma unroll
    for (int i = 0; i < 2; i++)
#pragma unroll
        for (int j = 0; j < 20; j++)
#pragma unroll
            for (int q = 0; q < 4; q++) acc[i][j][q] = 0.f;

    // ---------- phase 1: down (K = 640) ----------
    auto load_stage1 = [&](int ci) {
        uint32_t st = st1 + (uint32_t)(ci & 1) * STGB;
        int k0 = ci << 5;
        {
            int r = tid >> 1, j = tid & 1;
            cpa16(st + r * 80 + j * 32,      Ab + (size_t)r * CAT2 + k0 + j * 16);
            cpa16(st + r * 80 + j * 32 + 16, Ab + (size_t)r * CAT2 + k0 + j * 16 + 8);
        }
#pragma unroll
        for (int it = 0; it < 5; it++) {
            int idx = tid + it * 256;
            int r = idx >> 2, j = idx & 3;
            cpa16(st + 10240 + r * 80 + j * 16, wd + (size_t)r * CAT2 + k0 + j * 8);
        }
        asm volatile("cp.async.commit_group;" ::: "memory");
    };

    load_stage1(0);
    for (int i = 0; i < 20; i++) {
        if (i + 1 < 20) {
            load_stage1(i + 1);
            asm volatile("cp.async.wait_group 1;" ::: "memory");
        } else {
            asm volatile("cp.async.wait_group 0;" ::: "memory");
        }
        __syncthreads();
        uint32_t st = st1 + (uint32_t)(i & 1) * STGB;
#pragma unroll
        for (int kk = 0; kk < 2; kk++) {
            uint32_t ah[2][4];
#pragma unroll
            for (int mf = 0; mf < 2; mf++) {
                uint32_t ad = st + (uint32_t)(m0 + mf * 16 + a_r) * 80 + kk * 32 + a_c;
                LDM4(ah[mf], ad);
            }
#pragma unroll
            for (int np = 0; np < 10; np++) {
                uint32_t bh[4];
                uint32_t bd = st + 10240 + (uint32_t)(ng * 160 + np * 16 + b_r) * 80 + kk * 32 + b_c;
                LDM4(bh, bd);
#pragma unroll
                for (int mf = 0; mf < 2; mf++)
#pragma unroll
                    for (int h = 0; h < 2; h++)
                        MMA_F16(acc[mf][np * 2 + h], ah[mf], bh + 2 * h);
            }
        }
        __syncthreads();
    }

    // prefetch phase-2 B stage 0 (wu chunk 0)
    {
#pragma unroll
        for (int it = 0; it < 5; it++) {
            int idx = tid + it * 256;
            int r = idx >> 2, j = idx & 3;
            cpa16(st2 + r * 80 + j * 16, wu + (size_t)r * COUT + j * 8);
        }
        asm volatile("cp.async.commit_group;" ::: "memory");
    }

    // convert acc -> D1 fp16 in A-layout smem
#pragma unroll
    for (int mf = 0; mf < 2; mf++)
#pragma unroll
        for (int nf = 0; nf < 20; nf++) {
            int r0 = m0 + mf * 16 + (lane >> 2);
            int nc = ng * 160 + nf * 8 + 2 * (lane & 3);
            uint32_t base = d1 + (uint32_t)(nc >> 5) * 10240 + (nc & 31) * 2;
            *(uint32_t*)(uintptr_t)0; // placeholder removed below
            asm volatile("st.shared.b32 [%0], %1;" ::
                "r"(base + (uint32_t)r0 * 80),
                "r"(hpack(__float2half_rn(acc[mf][nf][0]), __float2half_rn(acc[mf][nf][1]))));
            asm volatile("st.shared.b32 [%0], %1;" ::
                "r"(base + (uint32_t)(r0 + 8) * 80),
                "r"(hpack(__float2half_rn(acc[mf][nf][2]), __float2half_rn(acc[mf][nf][3]))));
        }
    __syncthreads();

    // reset acc
#pragma unroll
    for (int i = 0; i < 2; i++)
#pragma unroll
        for (int j = 0; j < 20; j++)
#pragma unroll
            for (int q = 0; q < 4; q++) acc[i][j][q] = 0.f;

    // ---------- phase 2: up (K = 320, A from smem D1) ----------
    auto load_stage2 = [&](int ci) {
        uint32_t st = st2 + (uint32_t)(ci & 1) * 25600;
        int k0 = ci << 5;
#pragma unroll
        for (int it = 0; it < 5; it++) {
            int idx = tid + it * 256;
            int r = idx >> 2, j = idx & 3;
            cpa16(st + r * 80 + j * 16, wu + (size_t)r * COUT + k0 + j * 8);
        }
        asm volatile("cp.async.commit_group;" ::: "memory");
    };

    for (int i = 0; i < 10; i++) {
        if (i + 1 < 10) {
            load_stage2(i + 1);
            asm volatile("cp.async.wait_group 1;" ::: "memory");
        } else {
            asm volatile("cp.async.wait_group 0;" ::: "memory");
        }
        __syncthreads();
        uint32_t stB = st2 + (uint32_t)(i & 1) * 25600;
#pragma unroll
        for (int kk = 0; kk < 2; kk++) {
            uint32_t ah[2][4];
#pragma unroll
            for (int mf = 0; mf < 2; mf++) {
                uint32_t ad = d1 + (uint32_t)i * 10240 + (uint32_t)(m0 + mf * 16 + a_r) * 80 + kk * 32 + a_c;
                LDM4(ah[mf], ad);
            }
#pragma unroll
            for (int np = 0; np < 10; np++) {
                uint32_t bh[4];
                uint32_t bd = stB + (uint32_t)(ng * 160 + np * 16 + b_r) * 80 + kk * 32 + b_c;
                LDM4(bh, bd);
#pragma unroll
                for (int mf = 0; mf < 2; mf++)
#pragma unroll
                    for (int h = 0; h < 2; h++)
                        MMA_F16(acc[mf][np * 2 + h], ah[mf], bh + 2 * h);
            }
        }
        __syncthreads();
    }

    // ---------- epilogue: out = hF + scale*acc ----------
    float sc = *scalep;
    for (int g = 0; g < 2; g++) {
        if (ng == g) {
#pragma unroll
            for (int mf = 0; mf < 2; mf++)
#pragma unroll
                for (int nf = 0; nf < 20; nf++) {
                    int pr = m0 + mf * 16 + (lane >> 2);
                    int nc = nf * 8 + 2 * (lane & 3);
                    fst[nc * 132 + pr]           = acc[mf][nf][0];
                    fst[(nc + 1) * 132 + pr]     = acc[mf][nf][1];
                    fst[nc * 132 + pr + 8]       = acc[mf][nf][2];
                    fst[(nc + 1) * 132 + pr + 8] = acc[mf][nf][3];
                }
        }
        __syncthreads();
        int chbase = g * 160;
        for (int idx = tid; idx < 160 * 128; idx += 256) {
            int n = idx >> 7, p = idx & 127;
            float v = fst[n * 132 + p];
            size_t o = (((size_t)b * COUT + chbase + n) << 12) + pix0 + p;
            out[o] = hF[o] + sc * v;
        }
        __syncthreads();
    }
}

// ---------------- launch ----------------
extern "C" void kernel_launch(void* const* d_in, const int* in_sizes, int n_in,
                              void* d_out, int out_size) {
    const float* x      = (const float*)d_in[0];
    const float* weight = (const float*)d_in[1];
    const float* bias   = (const float*)d_in[2];
    const float* w_down = (const float*)d_in[3];
    const float* w_up   = (const float*)d_in[4];
    const float* scale  = (const float*)d_in[5];
    const float* offset = (const float*)d_in[6];
    float* out = (float*)d_out;

    __half *Ac, *Ad, *wt, *wd, *wu, *ct;
    float *hF;
    cudaGetSymbolAddress((void**)&Ac, g_Ac); cudaGetSymbolAddress((void**)&Ad, g_Ad);
    cudaGetSymbolAddress((void**)&wt, g_wt); cudaGetSymbolAddress((void**)&wd, g_wd);
    cudaGetSymbolAddress((void**)&wu, g_wu);
    cudaGetSymbolAddress((void**)&ct, g_ct);
    cudaGetSymbolAddress((void**)&hF, g_hF);

    cudaFuncSetAttribute(im2col_fused, cudaFuncAttributeMaxDynamicSharedMemorySize, SMEMB_IM);
    cudaFuncSetAttribute(gemm_big,     cudaFuncAttributeMaxDynamicSharedMemorySize, SMEMB_BIG);
    cudaFuncSetAttribute(gemm_downup,  cudaFuncAttributeMaxDynamicSharedMemorySize, SMEMB_DU);

    // launch #1
    precompute<<<(9 * HW + 255) / 256, 256>>>(offset);
    // launch #2
    prep_w<<<(NW1 + NW2 + NW3 + 255) / 256, 256>>>(weight, w_down, w_up, wt, wd, wu);
    // launch #3
    im2col_fused<<<dim3(40, BATCH), 256, SMEMB_IM>>>(x, Ac, Ad);
    // launch #4 (profiled): big dual GEMM
    gemm_big<<<dim3(HW / 128, 2, BATCH), 256, SMEMB_BIG>>>(Ad, Ac, wt, bias, hF, ct);
    // launch #5: fused down+up
    gemm_downup<<<dim3(HW / 128, BATCH), 256, SMEMB_DU>>>(ct, wd, wu, hF, out, scale);
}

// round 9
// speedup vs baseline: 1.2716x; 1.2716x over previous
#include <cuda_runtime.h>
#include <cuda_fp16.h>
#include <cstdint>

#define BATCH 4
#define CIN   320
#define COUT  320
#define HW    4096
#define CK    2880           // K = c*9 + k (native weight layout)
#define CAT2  640
// GEMM stage: A 128x80B = 10240 ; B 160x80B = 12800 ; total 23040; 3 stages
#define STGB  23040
#define SMEMB 69120
#define SMEMB_IM 131072

// ---------------- device scratch ----------------
__device__ __half g_Ac[(size_t)BATCH*HW*CK];
__device__ __half g_Ad[(size_t)BATCH*HW*CK];
__device__ __half g_wt[COUT*CK];
__device__ __half g_wd[COUT*CAT2];
__device__ __half g_wu[COUT*COUT];
__device__ __half g_ct[(size_t)BATCH*HW*CAT2];
__device__ __half g_dn[(size_t)BATCH*HW*COUT];
__device__ float  g_hF[(size_t)BATCH*COUT*HW];
__device__ int    g_ci[9*HW];
__device__ float  g_cw[9*HW];
__device__ int4   g_idf[9*HW];
__device__ float4 g_wdf[9*HW];

// ---------------- helpers ----------------
__device__ __forceinline__ uint32_t smem_u32(const void* p) {
    uint32_t a;
    asm("{ .reg .u64 t; cvta.to.shared.u64 t, %1; cvt.u32.u64 %0, t; }" : "=r"(a) : "l"(p));
    return a;
}
__device__ __forceinline__ void cpa16(uint32_t dst, const void* src) {
    asm volatile("cp.async.cg.shared.global [%0], [%1], 16;" :: "r"(dst), "l"(src));
}
#define LDM4(r, addr) \
    asm volatile("ldmatrix.sync.aligned.m8n8.x4.shared.b16 {%0,%1,%2,%3}, [%4];" \
        : "=r"((r)[0]), "=r"((r)[1]), "=r"((r)[2]), "=r"((r)[3]) : "r"(addr))
#define MMA_F16(c, a, bq) \
    asm volatile("mma.sync.aligned.m16n8k16.row.col.f32.f16.f16.f32 " \
        "{%0,%1,%2,%3}, {%4,%5,%6,%7}, {%8,%9}, {%0,%1,%2,%3};" \
        : "+f"((c)[0]), "+f"((c)[1]), "+f"((c)[2]), "+f"((c)[3]) \
        : "r"((a)[0]), "r"((a)[1]), "r"((a)[2]), "r"((a)[3]), "r"((bq)[0]), "r"((bq)[1]))

__device__ __forceinline__ uint32_t hpack(__half a, __half b) {
    return (uint32_t)__half_as_ushort(a) | ((uint32_t)__half_as_ushort(b) << 16);
}

// ---------------- launch #1: table precompute ----------------
__global__ void precompute(const float* __restrict__ off) {
    int t = blockIdx.x * 256 + threadIdx.x;
    if (t >= 9 * HW) return;
    int k = t >> 12, p = t & 4095;
    int r = p >> 6, c = p & 63;
    int rr = r + k / 3 - 1, qq = c + k % 3 - 1;
    bool vb = (rr >= 0 && rr < 64 && qq >= 0 && qq < 64);
    g_ci[t] = vb ? rr * 64 + qq : 0;
    g_cw[t] = vb ? 1.f : 0.f;
    float dy = off[((k*2+0) << 12) + p];
    float dx = off[((k*2+1) << 12) + p];
    float py = (float)rr + dy, px = (float)qq + dx;
    float y0f = floorf(py), x0f = floorf(px);
    int y0 = (int)y0f, x0 = (int)x0f;
    float wy = py - y0f, wx = px - x0f;
    float wv[4] = { (1.f-wy)*(1.f-wx), (1.f-wy)*wx, wy*(1.f-wx), wy*wx };
    int   idx[4]; float wgt[4];
#pragma unroll
    for (int j = 0; j < 4; j++) {
        int yy = y0 + (j >> 1), xx = x0 + (j & 1);
        bool ok = (yy >= 0 && yy < 64 && xx >= 0 && xx < 64);
        idx[j] = (min(max(yy,0),63) << 6) + min(max(xx,0),63);
        wgt[j] = ok ? wv[j] : 0.f;
    }
    g_idf[t] = make_int4(idx[0], idx[1], idx[2], idx[3]);
    g_wdf[t] = make_float4(wgt[0], wgt[1], wgt[2], wgt[3]);
}

// ---------------- launch #2: weight conversions ----------------
#define NW1 (COUT*CK)
#define NW2 (COUT*CAT2)
#define NW3 (COUT*COUT)
__global__ void prep_w(const float* __restrict__ w, const float* __restrict__ wdn,
                       const float* __restrict__ wup,
                       __half* wt, __half* wd, __half* wu) {
    int i = blockIdx.x * 256 + threadIdx.x;
    if (i < NW1) wt[i] = __float2half_rn(w[i]);
    else if (i < NW1 + NW2) wd[i - NW1] = __float2half_rn(wdn[i - NW1]);
    else if (i < NW1 + NW2 + NW3) wu[i - NW1 - NW2] = __float2half_rn(wup[i - NW1 - NW2]);
}

// ---------------- launch #3: fused im2col (R7 form) ----------------
__device__ __forceinline__ void store72(__half* __restrict__ H, const float* tv) {
#pragma unroll
    for (int q = 0; q < 9; q++) {
        uint32_t hh[4];
#pragma unroll
        for (int m = 0; m < 4; m++)
            hh[m] = hpack(__float2half_rn(tv[q*8 + 2*m]), __float2half_rn(tv[q*8 + 2*m + 1]));
        ((uint4*)H)[q] = make_uint4(hh[0], hh[1], hh[2], hh[3]);
    }
}

__global__ __launch_bounds__(256) void im2col_fused(
    const float* __restrict__ x,
    __half* __restrict__ Ac, __half* __restrict__ Ad)
{
    extern __shared__ float pl[];   // 8 channel planes = 128KB
    int b  = blockIdx.y;
    int c0 = blockIdx.x * 8;
    for (int idx = threadIdx.x; idx < 8 * 4096; idx += 256)
        pl[idx] = x[(((size_t)b * CIN + c0) << 12) + idx];
    __syncthreads();

    for (int p = threadIdx.x; p < 4096; p += 256) {
        float tv[72];
        size_t o = ((size_t)(b * HW) + p) * CK + (size_t)c0 * 9;
#pragma unroll
        for (int k = 0; k < 9; k++) {
            int   ci = g_ci[(k << 12) + p];
            float cw = g_cw[(k << 12) + p];
#pragma unroll
            for (int c = 0; c < 8; c++)
                tv[c*9 + k] = cw * pl[(c << 12) + ci];
        }
        store72(Ac + o, tv);
#pragma unroll
        for (int k = 0; k < 9; k++) {
            int4   di = g_idf[(k << 12) + p];
            float4 dw = g_wdf[(k << 12) + p];
#pragma unroll
            for (int c = 0; c < 8; c++) {
                const float* q = pl + (c << 12);
                tv[c*9 + k] = dw.x*q[di.x] + dw.y*q[di.y] + dw.z*q[di.z] + dw.w*q[di.w];
            }
        }
        store72(Ad + o, tv);
    }
}

// ---------------- HMMA GEMM: D[128 pix][160 ch slice], fp16, 2 CTA/SM ----------------
// MODE 0 (big): grid.y = asel*2+nsl; asel=0 -> A=def -> ct[:,0:320]; asel=1 -> A=conv
//               -> ct[:,320:640] + hF. +bias. nsl = 160-ch slice.
// MODE 1 (down): A=ct (K=640) -> dn, grid.y = nsl.
// MODE 2 (up):   A=dn (K=320) -> out = hF + scale*acc, grid.y = nsl.
template<int MODE>
__global__ void __launch_bounds__(256, 2) gemm_mma(
    const __half* __restrict__ A0, const __half* __restrict__ A1,
    const __half* __restrict__ B,
    int K, const float* __restrict__ bias, float* __restrict__ hF,
    __half* __restrict__ O, int ldo,
    float* __restrict__ out, const float* __restrict__ scalep)
{
    extern __shared__ char smem[];
    uint32_t sb = smem_u32(smem);
    float* fst = (float*)smem;                  // epilogue stage [80][132]
    int tid = threadIdx.x;
    int b = blockIdx.z;
    int pix0 = blockIdx.x * 128;
    int ys = blockIdx.y;
    int asel = (MODE == 0) ? (ys >> 1) : 0;
    int nsl  = (MODE == 0) ? (ys & 1) : ys;
    int NCH = K >> 5;

    const __half* Ab = ((MODE == 0 && asel) ? A1 : A0) + (size_t)(b * HW + pix0) * K;
    const __half* Bs = B + (size_t)(nsl * 160) * K;
    int cofs = ((MODE == 0 && asel) ? 320 : 0) + nsl * 160;   // for fp16 O writes

    int w = tid >> 5, lane = tid & 31;
    int m0 = (w & 3) * 32;
    int ngr = w >> 2;                 // 0/1: 80-ch group within the 160 slice
    int a_r = (lane & 7) + ((lane >> 3) & 1) * 8;
    int a_c = ((lane >> 4) & 1) * 16;
    int b_r = (lane & 7) + ((lane >> 4) & 1) * 8;
    int b_c = ((lane >> 3) & 1) * 16;

    float acc[2][10][4];
#pragma unroll
    for (int i = 0; i < 2; i++)
#pragma unroll
        for (int j = 0; j < 10; j++)
#pragma unroll
            for (int q = 0; q < 4; q++) acc[i][j][q] = 0.f;

    auto load_stage = [&](int ci) {
        uint32_t st = sb + (uint32_t)(ci % 3) * STGB;
        int k0 = ci << 5;
        {                                        // A: 128 rows x 64B
            int r = tid >> 1, j = tid & 1;
            cpa16(st + r * 80 + j * 32,      Ab + (size_t)r * K + k0 + j * 16);
            cpa16(st + r * 80 + j * 32 + 16, Ab + (size_t)r * K + k0 + j * 16 + 8);
        }
#pragma unroll
        for (int it = 0; it < 3; it++) {        // B: 160 rows x 64B = 640 x 16B
            int idx = tid + it * 256;
            if (idx < 640) {
                int r = idx >> 2, j = idx & 3;
                cpa16(st + 10240 + r * 80 + j * 16, Bs + (size_t)r * K + k0 + j * 8);
            }
        }
        asm volatile("cp.async.commit_group;" ::: "memory");
    };

    load_stage(0);
    load_stage(1);
    for (int i = 0; i < NCH; i++) {
        if (i + 2 < NCH) load_stage(i + 2);
        else asm volatile("cp.async.commit_group;" ::: "memory");
        asm volatile("cp.async.wait_group 2;" ::: "memory");
        __syncthreads();
        uint32_t st = sb + (uint32_t)(i % 3) * STGB;
#pragma unroll
        for (int kk = 0; kk < 2; kk++) {
            uint32_t ah[2][4];
#pragma unroll
            for (int mf = 0; mf < 2; mf++) {
                uint32_t ad = st + (uint32_t)(m0 + mf * 16 + a_r) * 80 + kk * 32 + a_c;
                LDM4(ah[mf], ad);
            }
#pragma unroll
            for (int np = 0; np < 5; np++) {
                uint32_t bh[4];
                uint32_t bd = st + 10240 + (uint32_t)(ngr * 80 + np * 16 + b_r) * 80 + kk * 32 + b_c;
                LDM4(bh, bd);
#pragma unroll
                for (int mf = 0; mf < 2; mf++)
#pragma unroll
                    for (int h = 0; h < 2; h++)
                        MMA_F16(acc[mf][np * 2 + h], ah[mf], bh + 2 * h);
            }
        }
        __syncthreads();
    }

    // ---- epilogue: 2 groups of 80 channels via smem [80][132] ----
    float sc = (MODE == 2) ? *scalep : 0.f;
    for (int g = 0; g < 2; g++) {
        if (ngr == g) {
#pragma unroll
            for (int mf = 0; mf < 2; mf++)
#pragma unroll
                for (int nf = 0; nf < 10; nf++) {
                    int pr = m0 + mf * 16 + (lane >> 2);
                    int nc = nf * 8 + 2 * (lane & 3);
                    fst[nc * 132 + pr]           = acc[mf][nf][0];
                    fst[(nc + 1) * 132 + pr]     = acc[mf][nf][1];
                    fst[nc * 132 + pr + 8]       = acc[mf][nf][2];
                    fst[(nc + 1) * 132 + pr + 8] = acc[mf][nf][3];
                }
        }
        __syncthreads();
        int chbase = nsl * 160 + g * 80;         // global channel base

        if ((MODE == 0 && asel == 1) || MODE == 2) {   // f32 ch-major path
            for (int idx = tid; idx < 80 * 128; idx += 256) {
                int n = idx >> 7, p = idx & 127;
                float v = fst[n * 132 + p];
                size_t o = (((size_t)b * COUT + chbase + n) << 12) + pix0 + p;
                if (MODE == 0) hF[o] = v + __ldg(bias + chbase + n);
                else           out[o] = hF[o] + sc * v;
            }
        }
        if (MODE <= 1) {                               // fp16 pixel-major path
            int p = tid >> 1, hf2 = tid & 1;
            size_t row = ((size_t)(b * HW) + pix0 + p) * ldo + cofs + g * 80 + hf2 * 40;
            uint32_t uh[20];
#pragma unroll
            for (int m = 0; m < 20; m++) {
                int n = hf2 * 40 + 2 * m;
                float v0 = fst[n * 132 + p], v1 = fst[(n + 1) * 132 + p];
                if (MODE == 0) {
                    v0 += __ldg(bias + chbase + n);
                    v1 += __ldg(bias + chbase + n + 1);
                }
                uh[m] = hpack(__float2half_rn(v0), __float2half_rn(v1));
            }
#pragma unroll
            for (int q = 0; q < 5; q++)
                ((uint4*)(O + row))[q] = make_uint4(uh[4*q], uh[4*q+1], uh[4*q+2], uh[4*q+3]);
        }
        __syncthreads();
    }
}

// ---------------- launch ----------------
extern "C" void kernel_launch(void* const* d_in, const int* in_sizes, int n_in,
                              void* d_out, int out_size) {
    const float* x      = (const float*)d_in[0];
    const float* weight = (const float*)d_in[1];
    const float* bias   = (const float*)d_in[2];
    const float* w_down = (const float*)d_in[3];
    const float* w_up   = (const float*)d_in[4];
    const float* scale  = (const float*)d_in[5];
    const float* offset = (const float*)d_in[6];
    float* out = (float*)d_out;

    __half *Ac, *Ad, *wt, *wd, *wu, *ct, *dn;
    float *hF;
    cudaGetSymbolAddress((void**)&Ac, g_Ac); cudaGetSymbolAddress((void**)&Ad, g_Ad);
    cudaGetSymbolAddress((void**)&wt, g_wt); cudaGetSymbolAddress((void**)&wd, g_wd);
    cudaGetSymbolAddress((void**)&wu, g_wu);
    cudaGetSymbolAddress((void**)&ct, g_ct); cudaGetSymbolAddress((void**)&dn, g_dn);
    cudaGetSymbolAddress((void**)&hF, g_hF);

    cudaFuncSetAttribute(im2col_fused, cudaFuncAttributeMaxDynamicSharedMemorySize, SMEMB_IM);
    cudaFuncSetAttribute(gemm_mma<0>, cudaFuncAttributeMaxDynamicSharedMemorySize, SMEMB);
    cudaFuncSetAttribute(gemm_mma<1>, cudaFuncAttributeMaxDynamicSharedMemorySize, SMEMB);
    cudaFuncSetAttribute(gemm_mma<2>, cudaFuncAttributeMaxDynamicSharedMemorySize, SMEMB);

    precompute<<<(9 * HW + 255) / 256, 256>>>(offset);
    prep_w<<<(NW1 + NW2 + NW3 + 255) / 256, 256>>>(weight, w_down, w_up, wt, wd, wu);
    im2col_fused<<<dim3(40, BATCH), 256, SMEMB_IM>>>(x, Ac, Ad);

    // big dual GEMM: grid.y = asel*2 + nsl
    gemm_mma<0><<<dim3(HW / 128, 4, BATCH), 256, SMEMB>>>(
        Ad, Ac, wt, CK, bias, hF, ct, CAT2, nullptr, nullptr);
    // down = w_down @ cat -> dn
    gemm_mma<1><<<dim3(HW / 128, 2, BATCH), 256, SMEMB>>>(
        ct, nullptr, wd, CAT2, nullptr, nullptr, dn, COUT, nullptr, nullptr);
    // out = hF + scale * (w_up @ dn)
    gemm_mma<2><<<dim3(HW / 128, 2, BATCH), 256, SMEMB>>>(
        dn, nullptr, wu, COUT, nullptr, hF, nullptr, 0, out, scale);
}